// round 1
// baseline (speedup 1.0000x reference)
#include <cuda_runtime.h>
#include <math.h>

#define NN 200000
#define EE 400000
#define GG 8000
#define HH 4
#define CC 64
#define NBP 200           // batchnorm partial blocks
#define NB1 196           // scan blocks (196*1024 >= 200000)

// ---------------- device scratch ----------------
__device__ float g_h [NN*64];
__device__ float g_hn[NN*64];
__device__ float g_s [NN*256];
__device__ float g_as[NN*4];
__device__ float g_ad[NN*4];
__device__ float g_ae[EE*4];
__device__ int   g_deg[NN];
__device__ int   g_rowstart[NN+1];
__device__ int   g_cursor[NN];
__device__ int   g_eid[EE];
__device__ int   g_tmpscan[NN];
__device__ int   g_bsum[256];
__device__ int   g_boff[256];
__device__ float g_bnpart[NBP*128];
__device__ float g_scale[64];
__device__ float g_shift[64];
__device__ float g_vsrc[256];
__device__ float g_vdst[256];
__device__ float g_wedge[32];

#define FULLM 0xffffffffu

// ---------------- CSR build ----------------
__global__ void k_zero_deg() {
    int i = blockIdx.x * 256 + threadIdx.x;
    if (i < NN) g_deg[i] = 0;
}

__global__ void k_degree(const int* __restrict__ ei) {
    int e = blockIdx.x * 256 + threadIdx.x;
    if (e < EE) atomicAdd(&g_deg[ei[EE + e]], 1);
}

__global__ void k_scan1() {
    __shared__ int sh[1024];
    int tid = threadIdx.x;
    int t = blockIdx.x * 1024 + tid;
    int v = (t < NN) ? g_deg[t] : 0;
    sh[tid] = v;
    __syncthreads();
    for (int off = 1; off < 1024; off <<= 1) {
        int add = (tid >= off) ? sh[tid - off] : 0;
        __syncthreads();
        sh[tid] += add;
        __syncthreads();
    }
    if (t < NN) g_tmpscan[t] = sh[tid];
    if (tid == 1023) g_bsum[blockIdx.x] = sh[1023];
}

__global__ void k_scan2() {
    __shared__ int sh[256];
    int tid = threadIdx.x;
    int v = (tid < NB1) ? g_bsum[tid] : 0;
    sh[tid] = v;
    __syncthreads();
    for (int off = 1; off < 256; off <<= 1) {
        int add = (tid >= off) ? sh[tid - off] : 0;
        __syncthreads();
        sh[tid] += add;
        __syncthreads();
    }
    if (tid < NB1) g_boff[tid] = sh[tid] - v;   // exclusive
}

__global__ void k_scan3() {
    int tid = threadIdx.x;
    int t = blockIdx.x * 1024 + tid;
    if (t < NN) {
        int rs = g_boff[blockIdx.x] + g_tmpscan[t] - g_deg[t];
        g_rowstart[t] = rs;
        g_cursor[t] = rs;
    }
    if (t == 0) g_rowstart[NN] = EE;
}

__global__ void k_fill(const int* __restrict__ ei) {
    int e = blockIdx.x * 256 + threadIdx.x;
    if (e < EE) {
        int d = ei[EE + e];
        int p = atomicAdd(&g_cursor[d], 1);
        g_eid[p] = e;
    }
}

// ---------------- input projection ----------------
__global__ void k_lin(const float* __restrict__ x,
                      const float* __restrict__ lin_w,
                      const float* __restrict__ lin_b) {
    __shared__ float ws[2048];
    __shared__ float xt[8 * 32];
    int c = threadIdx.x;            // 0..63
    int r = threadIdx.y;            // 0..7
    int tid = c + r * 64;           // 0..511
    for (int i = tid; i < 2048; i += 512) ws[i] = lin_w[i];
    if (tid < 256) {
        int rr = tid >> 5, kk = tid & 31;
        xt[rr * 32 + kk] = x[(blockIdx.x * 8 + rr) * 32 + kk];
    }
    __syncthreads();
    float a = lin_b[c];
    #pragma unroll
    for (int k = 0; k < 32; k++) a = fmaf(xt[r * 32 + k], ws[k * 64 + c], a);
    g_h[(blockIdx.x * 8 + r) * 64 + c] = fmaxf(a, 0.0f);
}

// ---------------- batchnorm ----------------
__global__ void k_bnpart() {
    __shared__ float sh1[4][64];
    __shared__ float sh2[4][64];
    int c = threadIdx.x, ty = threadIdx.y;
    float s1 = 0.f, s2 = 0.f;
    for (int n = blockIdx.x * 4 + ty; n < NN; n += NBP * 4) {
        float v = g_h[n * 64 + c];
        s1 += v; s2 += v * v;
    }
    sh1[ty][c] = s1; sh2[ty][c] = s2;
    __syncthreads();
    if (ty == 0) {
        float t1 = sh1[0][c] + sh1[1][c] + sh1[2][c] + sh1[3][c];
        float t2 = sh2[0][c] + sh2[1][c] + sh2[2][c] + sh2[3][c];
        g_bnpart[blockIdx.x * 128 + c] = t1;
        g_bnpart[blockIdx.x * 128 + 64 + c] = t2;
    }
}

__global__ void k_bnfin(int l,
                        const float* __restrict__ gamma,
                        const float* __restrict__ beta,
                        const float* __restrict__ conv_w,
                        const float* __restrict__ conv_we,
                        const float* __restrict__ att_src,
                        const float* __restrict__ att_dst,
                        const float* __restrict__ att_edge) {
    int tid = threadIdx.x;
    if (tid < 64) {
        float s1 = 0.f, s2 = 0.f;
        for (int b = 0; b < NBP; b++) {
            s1 += g_bnpart[b * 128 + tid];
            s2 += g_bnpart[b * 128 + 64 + tid];
        }
        float mu = s1 / (float)NN;
        float var = s2 / (float)NN - mu * mu;
        float sc = gamma[l * 64 + tid] * rsqrtf(var + 1e-5f);
        g_scale[tid] = sc;
        g_shift[tid] = beta[l * 64 + tid] - mu * sc;
    }
    // fold attention vectors: v_src[h][k] = sum_c W[k][h*64+c]*att_src[h][c]
    {
        int h = tid >> 6, k = tid & 63;
        const float* W = conv_w + l * 16384 + k * 256 + h * 64;
        const float* as = att_src + l * 256 + h * 64;
        const float* ad = att_dst + l * 256 + h * 64;
        float vs = 0.f, vd = 0.f;
        #pragma unroll 8
        for (int c = 0; c < 64; c++) { float w = W[c]; vs += w * as[c]; vd += w * ad[c]; }
        g_vsrc[tid] = vs;
        g_vdst[tid] = vd;
    }
    if (tid < 32) {
        int h = tid >> 3, j = tid & 7;
        const float* We = conv_we + l * 2048 + j * 256 + h * 64;
        const float* ae = att_edge + l * 256 + h * 64;
        float we = 0.f;
        #pragma unroll 8
        for (int c = 0; c < 64; c++) we += We[c] * ae[c];
        g_wedge[tid] = we;
    }
}

// BN apply -> hn, plus per-node attention scores a_s, a_d
__global__ void k_bnapply() {
    __shared__ float sp[4][2][8];
    int c = threadIdx.x, ty = threadIdx.y;
    int n = blockIdx.x * 4 + ty;
    float hv = g_h[n * 64 + c] * g_scale[c] + g_shift[c];
    g_hn[n * 64 + c] = hv;
    float v[8];
    #pragma unroll
    for (int h = 0; h < 4; h++) {
        v[h]     = hv * g_vsrc[h * 64 + c];
        v[4 + h] = hv * g_vdst[h * 64 + c];
    }
    #pragma unroll
    for (int off = 16; off > 0; off >>= 1) {
        #pragma unroll
        for (int i = 0; i < 8; i++) v[i] += __shfl_down_sync(FULLM, v[i], off);
    }
    if ((c & 31) == 0) {
        #pragma unroll
        for (int i = 0; i < 8; i++) sp[ty][c >> 5][i] = v[i];
    }
    __syncthreads();
    if (c < 8) {
        float val = sp[ty][0][c] + sp[ty][1][c];
        if (c < 4) g_as[n * 4 + c] = val;
        else       g_ad[n * 4 + c - 4] = val;
    }
}

// edge score a_e
__global__ void k_aedge(const float* __restrict__ edge_attr) {
    __shared__ float we[32];
    int tid = threadIdx.x;
    if (tid < 32) we[tid] = g_wedge[tid];
    __syncthreads();
    int e = blockIdx.x * 256 + tid;
    if (e >= EE) return;
    float4 e0 = *(const float4*)(edge_attr + e * 8);
    float4 e1 = *(const float4*)(edge_attr + e * 8 + 4);
    float o[4];
    #pragma unroll
    for (int h = 0; h < 4; h++) {
        const float* w = &we[h * 8];
        o[h] = e0.x*w[0] + e0.y*w[1] + e0.z*w[2] + e0.w*w[3]
             + e1.x*w[4] + e1.y*w[5] + e1.z*w[6] + e1.w*w[7];
    }
    *(float4*)&g_ae[e * 4] = make_float4(o[0], o[1], o[2], o[3]);
}

__device__ __forceinline__ float lrelu(float a) { return a > 0.f ? a : 0.2f * a; }

// fused per-node: segment softmax + weighted aggregation of hn[src] -> s[n][h][c]
__global__ void k_conv(const int* __restrict__ ei) {
    int tid = threadIdx.x;
    int wid = tid >> 5, lane = tid & 31;
    int n = blockIdx.x * 8 + wid;
    int start = g_rowstart[n];
    int end   = g_rowstart[n + 1];
    float4 ad4 = *(const float4*)&g_ad[n * 4];
    // pass 1: max over incoming edges (lane-strided + warp reduce)
    float m0 = -1e30f, m1 = -1e30f, m2 = -1e30f, m3 = -1e30f;
    for (int i = start + lane; i < end; i += 32) {
        int e = g_eid[i];
        int sv = ei[e];
        float4 as4 = *(const float4*)&g_as[sv * 4];
        float4 ae4 = *(const float4*)&g_ae[e * 4];
        m0 = fmaxf(m0, lrelu(as4.x + ad4.x + ae4.x));
        m1 = fmaxf(m1, lrelu(as4.y + ad4.y + ae4.y));
        m2 = fmaxf(m2, lrelu(as4.z + ad4.z + ae4.z));
        m3 = fmaxf(m3, lrelu(as4.w + ad4.w + ae4.w));
    }
    #pragma unroll
    for (int off = 16; off > 0; off >>= 1) {
        m0 = fmaxf(m0, __shfl_xor_sync(FULLM, m0, off));
        m1 = fmaxf(m1, __shfl_xor_sync(FULLM, m1, off));
        m2 = fmaxf(m2, __shfl_xor_sync(FULLM, m2, off));
        m3 = fmaxf(m3, __shfl_xor_sync(FULLM, m3, off));
    }
    // pass 2: exp weights + aggregate
    float den0 = 0.f, den1 = 0.f, den2 = 0.f, den3 = 0.f;
    float aA0 = 0.f, aA1 = 0.f, aA2 = 0.f, aA3 = 0.f;
    float aB0 = 0.f, aB1 = 0.f, aB2 = 0.f, aB3 = 0.f;
    for (int i = start; i < end; i++) {
        int e = g_eid[i];
        int sv = ei[e];
        float4 as4 = *(const float4*)&g_as[sv * 4];
        float4 ae4 = *(const float4*)&g_ae[e * 4];
        float w0 = __expf(lrelu(as4.x + ad4.x + ae4.x) - m0);
        float w1 = __expf(lrelu(as4.y + ad4.y + ae4.y) - m1);
        float w2 = __expf(lrelu(as4.z + ad4.z + ae4.z) - m2);
        float w3 = __expf(lrelu(as4.w + ad4.w + ae4.w) - m3);
        den0 += w0; den1 += w1; den2 += w2; den3 += w3;
        float ha = g_hn[sv * 64 + lane];
        float hb = g_hn[sv * 64 + 32 + lane];
        aA0 = fmaf(w0, ha, aA0); aB0 = fmaf(w0, hb, aB0);
        aA1 = fmaf(w1, ha, aA1); aB1 = fmaf(w1, hb, aB1);
        aA2 = fmaf(w2, ha, aA2); aB2 = fmaf(w2, hb, aB2);
        aA3 = fmaf(w3, ha, aA3); aB3 = fmaf(w3, hb, aB3);
    }
    float i0 = 1.f / (den0 + 1e-16f);
    float i1 = 1.f / (den1 + 1e-16f);
    float i2 = 1.f / (den2 + 1e-16f);
    float i3 = 1.f / (den3 + 1e-16f);
    int base = n * 256 + lane;
    g_s[base +   0] = aA0 * i0;  g_s[base +  32] = aB0 * i0;
    g_s[base +  64] = aA1 * i1;  g_s[base +  96] = aB1 * i1;
    g_s[base + 128] = aA2 * i2;  g_s[base + 160] = aB2 * i2;
    g_s[base + 192] = aA3 * i3;  g_s[base + 224] = aB3 * i3;
}

// GEMM: h_new = relu( (1/H) * sum_{h,k} s[n,h,k]*W[k,h*64+c] + bias ) + h_old
__global__ void k_gemm(int l, const float* __restrict__ conv_w,
                       const float* __restrict__ conv_bias) {
    extern __shared__ float sm[];
    float* Wsh = sm;            // 16384 floats
    float* sSh = sm + 16384;    // 8192 floats (32 nodes)
    int tid = threadIdx.x;
    const float* Wg = conv_w + l * 16384;
    for (int i = tid; i < 16384; i += 256) Wsh[i] = Wg[i];
    int nb = blockIdx.x * 32;
    const float* sg = g_s + (size_t)nb * 256;
    for (int i = tid; i < 8192; i += 256) sSh[i] = sg[i];
    __syncthreads();

    int cg = tid & 31;     // channel pair group
    int ng = tid >> 5;     // node group (0..7), each does 4 nodes
    int c0 = cg * 2;
    float acc[4][2] = {{0.f,0.f},{0.f,0.f},{0.f,0.f},{0.f,0.f}};
    #pragma unroll
    for (int h = 0; h < 4; h++) {
        #pragma unroll
        for (int kt = 0; kt < 64; kt += 4) {
            float2 w0 = *(const float2*)&Wsh[(kt + 0) * 256 + h * 64 + c0];
            float2 w1 = *(const float2*)&Wsh[(kt + 1) * 256 + h * 64 + c0];
            float2 w2 = *(const float2*)&Wsh[(kt + 2) * 256 + h * 64 + c0];
            float2 w3 = *(const float2*)&Wsh[(kt + 3) * 256 + h * 64 + c0];
            #pragma unroll
            for (int j = 0; j < 4; j++) {
                float4 sv = *(const float4*)&sSh[(ng * 4 + j) * 256 + h * 64 + kt];
                acc[j][0] = fmaf(sv.x, w0.x, acc[j][0]);
                acc[j][1] = fmaf(sv.x, w0.y, acc[j][1]);
                acc[j][0] = fmaf(sv.y, w1.x, acc[j][0]);
                acc[j][1] = fmaf(sv.y, w1.y, acc[j][1]);
                acc[j][0] = fmaf(sv.z, w2.x, acc[j][0]);
                acc[j][1] = fmaf(sv.z, w2.y, acc[j][1]);
                acc[j][0] = fmaf(sv.w, w3.x, acc[j][0]);
                acc[j][1] = fmaf(sv.w, w3.y, acc[j][1]);
            }
        }
    }
    #pragma unroll
    for (int j = 0; j < 4; j++) {
        int node = nb + ng * 4 + j;
        #pragma unroll
        for (int cc = 0; cc < 2; cc++) {
            int c = c0 + cc;
            float o = fmaxf(acc[j][cc] * 0.25f + conv_bias[l * 64 + c], 0.0f);
            g_h[node * 64 + c] = o + g_h[node * 64 + c];  // skip connection
        }
    }
}

// ---------------- pooling + MLP head (fused, deterministic) ----------------
__device__ __forceinline__ int lower_bound_dev(const int* b, int n, int v) {
    int lo = 0, hi = n;
    while (lo < hi) {
        int mid = (lo + hi) >> 1;
        if (b[mid] < v) lo = mid + 1; else hi = mid;
    }
    return lo;
}

__global__ void k_pool_mlp(const int* __restrict__ batch,
                           const float* __restrict__ fc1_w,
                           const float* __restrict__ fc1_b,
                           const float* __restrict__ fc2_w,
                           const float* __restrict__ fc2_b,
                           float* __restrict__ out) {
    __shared__ float ps[64];
    __shared__ float r2[2];
    int g = blockIdx.x;
    int tid = threadIdx.x;
    int start = lower_bound_dev(batch, NN, g);
    int end   = lower_bound_dev(batch, NN, g + 1);
    float s = 0.f;
    for (int n = start; n < end; n++) s += g_h[n * 64 + tid];
    ps[tid] = s;
    __syncthreads();
    float z = fc1_b[tid];
    #pragma unroll 8
    for (int k = 0; k < 64; k++) z = fmaf(ps[k], fc1_w[k * 64 + tid], z);
    z = fmaxf(z, 0.0f);
    float p = z * fc2_w[tid];
    #pragma unroll
    for (int off = 16; off > 0; off >>= 1) p += __shfl_down_sync(FULLM, p, off);
    if ((tid & 31) == 0) r2[tid >> 5] = p;
    __syncthreads();
    if (tid == 0) out[g] = fmaxf(r2[0] + r2[1] + fc2_b[0], 0.0f);
}

// ---------------- launcher ----------------
extern "C" void kernel_launch(void* const* d_in, const int* in_sizes, int n_in,
                              void* d_out, int out_size) {
    const float* x         = (const float*)d_in[0];
    const int*   ei        = (const int*)  d_in[1];
    const float* edge_attr = (const float*)d_in[2];
    const int*   batch     = (const int*)  d_in[3];
    const float* lin_w     = (const float*)d_in[4];
    const float* lin_b     = (const float*)d_in[5];
    const float* bn_gamma  = (const float*)d_in[6];
    const float* bn_beta   = (const float*)d_in[7];
    const float* conv_w    = (const float*)d_in[8];
    const float* conv_we   = (const float*)d_in[9];
    const float* att_src   = (const float*)d_in[10];
    const float* att_dst   = (const float*)d_in[11];
    const float* att_edge  = (const float*)d_in[12];
    const float* conv_bias = (const float*)d_in[13];
    const float* fc1_w     = (const float*)d_in[14];
    const float* fc1_b     = (const float*)d_in[15];
    const float* fc2_w     = (const float*)d_in[16];
    const float* fc2_b     = (const float*)d_in[17];
    float* out = (float*)d_out;

    cudaFuncSetAttribute(k_gemm, cudaFuncAttributeMaxDynamicSharedMemorySize, 98304);

    // CSR build (reused by all 3 layers)
    k_zero_deg<<<(NN + 255) / 256, 256>>>();
    k_degree<<<(EE + 255) / 256, 256>>>(ei);
    k_scan1<<<NB1, 1024>>>();
    k_scan2<<<1, 256>>>();
    k_scan3<<<NB1, 1024>>>();
    k_fill<<<(EE + 255) / 256, 256>>>(ei);

    // input projection
    k_lin<<<NN / 8, dim3(64, 8)>>>(x, lin_w, lin_b);

    for (int l = 0; l < 3; l++) {
        k_bnpart<<<NBP, dim3(64, 4)>>>();
        k_bnfin<<<1, 256>>>(l, bn_gamma, bn_beta, conv_w, conv_we,
                            att_src, att_dst, att_edge);
        k_bnapply<<<NN / 4, dim3(64, 4)>>>();
        k_aedge<<<(EE + 255) / 256, 256>>>(edge_attr);
        k_conv<<<NN / 8, 256>>>(ei);
        k_gemm<<<NN / 32, 256, 98304>>>(l, conv_w, conv_bias);
    }

    k_pool_mlp<<<GG, 64>>>(batch, fc1_w, fc1_b, fc2_w, fc2_b, out);
}

// round 2
// speedup vs baseline: 1.2986x; 1.2986x over previous
#include <cuda_runtime.h>
#include <math.h>

#define NN 200000
#define EE 400000
#define GG 8000
#define NBP 200           // batchnorm partial blocks
#define NB1 196           // scan blocks (196*1024 >= 200000)

// ---------------- device scratch ----------------
__device__ float g_h [NN*64];
__device__ float g_hn[NN*64];
__device__ float g_as[NN*4];
__device__ float g_ad[NN*4];
__device__ float g_ae[EE*4];
__device__ int   g_deg[NN];
__device__ int   g_rowstart[NN+1];
__device__ int   g_cursor[NN];
__device__ int   g_eid[EE];
__device__ int   g_tmpscan[NN];
__device__ int   g_bsum[256];
__device__ int   g_boff[256];
__device__ float g_bnpart[NBP*128];
__device__ float g_scale[64];
__device__ float g_shift[64];
__device__ float g_vsrc[256];
__device__ float g_vdst[256];
__device__ float g_wedge[32];

#define FULLM 0xffffffffu

// ---------------- f32x2 packed math helpers ----------------
__device__ __forceinline__ unsigned long long pk2(float a, float b) {
    unsigned long long r;
    asm("mov.b64 %0, {%1, %2};" : "=l"(r) : "f"(a), "f"(b));
    return r;
}
__device__ __forceinline__ void fma2(unsigned long long& d,
                                     unsigned long long a, unsigned long long b) {
    asm("fma.rn.f32x2 %0, %1, %2, %0;" : "+l"(d) : "l"(a), "l"(b));
}
__device__ __forceinline__ float2 upk2(unsigned long long v) {
    float2 r;
    asm("mov.b64 {%0, %1}, %2;" : "=f"(r.x), "=f"(r.y) : "l"(v));
    return r;
}

// ---------------- CSR build ----------------
__global__ void k_zero_deg() {
    int i = blockIdx.x * 256 + threadIdx.x;
    if (i < NN) g_deg[i] = 0;
}

__global__ void k_degree(const int* __restrict__ ei) {
    int e = blockIdx.x * 256 + threadIdx.x;
    if (e < EE) atomicAdd(&g_deg[ei[EE + e]], 1);
}

__global__ void k_scan1() {
    __shared__ int sh[1024];
    int tid = threadIdx.x;
    int t = blockIdx.x * 1024 + tid;
    int v = (t < NN) ? g_deg[t] : 0;
    sh[tid] = v;
    __syncthreads();
    for (int off = 1; off < 1024; off <<= 1) {
        int add = (tid >= off) ? sh[tid - off] : 0;
        __syncthreads();
        sh[tid] += add;
        __syncthreads();
    }
    if (t < NN) g_tmpscan[t] = sh[tid];
    if (tid == 1023) g_bsum[blockIdx.x] = sh[1023];
}

__global__ void k_scan2() {
    __shared__ int sh[256];
    int tid = threadIdx.x;
    int v = (tid < NB1) ? g_bsum[tid] : 0;
    sh[tid] = v;
    __syncthreads();
    for (int off = 1; off < 256; off <<= 1) {
        int add = (tid >= off) ? sh[tid - off] : 0;
        __syncthreads();
        sh[tid] += add;
        __syncthreads();
    }
    if (tid < NB1) g_boff[tid] = sh[tid] - v;   // exclusive
}

__global__ void k_scan3() {
    int tid = threadIdx.x;
    int t = blockIdx.x * 1024 + tid;
    if (t < NN) {
        int rs = g_boff[blockIdx.x] + g_tmpscan[t] - g_deg[t];
        g_rowstart[t] = rs;
        g_cursor[t] = rs;
    }
    if (t == 0) g_rowstart[NN] = EE;
}

__global__ void k_fill(const int* __restrict__ ei) {
    int e = blockIdx.x * 256 + threadIdx.x;
    if (e < EE) {
        int d = ei[EE + e];
        int p = atomicAdd(&g_cursor[d], 1);
        g_eid[p] = e;
    }
}

// ---------------- input projection ----------------
__global__ void k_lin(const float* __restrict__ x,
                      const float* __restrict__ lin_w,
                      const float* __restrict__ lin_b) {
    __shared__ float ws[2048];
    __shared__ float xt[8 * 32];
    int c = threadIdx.x;            // 0..63
    int r = threadIdx.y;            // 0..7
    int tid = c + r * 64;           // 0..511
    for (int i = tid; i < 2048; i += 512) ws[i] = lin_w[i];
    if (tid < 256) {
        int rr = tid >> 5, kk = tid & 31;
        xt[rr * 32 + kk] = x[(blockIdx.x * 8 + rr) * 32 + kk];
    }
    __syncthreads();
    float a = lin_b[c];
    #pragma unroll
    for (int k = 0; k < 32; k++) a = fmaf(xt[r * 32 + k], ws[k * 64 + c], a);
    g_h[(blockIdx.x * 8 + r) * 64 + c] = fmaxf(a, 0.0f);
}

// ---------------- batchnorm ----------------
__global__ void k_bnpart() {
    __shared__ float sh1[4][64];
    __shared__ float sh2[4][64];
    int c = threadIdx.x, ty = threadIdx.y;
    float s1 = 0.f, s2 = 0.f;
    for (int n = blockIdx.x * 4 + ty; n < NN; n += NBP * 4) {
        float v = g_h[n * 64 + c];
        s1 += v; s2 += v * v;
    }
    sh1[ty][c] = s1; sh2[ty][c] = s2;
    __syncthreads();
    if (ty == 0) {
        float t1 = sh1[0][c] + sh1[1][c] + sh1[2][c] + sh1[3][c];
        float t2 = sh2[0][c] + sh2[1][c] + sh2[2][c] + sh2[3][c];
        g_bnpart[blockIdx.x * 128 + c] = t1;
        g_bnpart[blockIdx.x * 128 + 64 + c] = t2;
    }
}

__global__ void k_bnfin(int l,
                        const float* __restrict__ gamma,
                        const float* __restrict__ beta,
                        const float* __restrict__ conv_w,
                        const float* __restrict__ conv_we,
                        const float* __restrict__ att_src,
                        const float* __restrict__ att_dst,
                        const float* __restrict__ att_edge) {
    int tid = threadIdx.x;
    if (tid < 64) {
        float s1 = 0.f, s2 = 0.f;
        for (int b = 0; b < NBP; b++) {
            s1 += g_bnpart[b * 128 + tid];
            s2 += g_bnpart[b * 128 + 64 + tid];
        }
        float mu = s1 / (float)NN;
        float var = s2 / (float)NN - mu * mu;
        float sc = gamma[l * 64 + tid] * rsqrtf(var + 1e-5f);
        g_scale[tid] = sc;
        g_shift[tid] = beta[l * 64 + tid] - mu * sc;
    }
    // fold attention vectors: v_src[h][k] = sum_c W[k][h*64+c]*att_src[h][c]
    {
        int h = tid >> 6, k = tid & 63;
        const float* W = conv_w + l * 16384 + k * 256 + h * 64;
        const float* as = att_src + l * 256 + h * 64;
        const float* ad = att_dst + l * 256 + h * 64;
        float vs = 0.f, vd = 0.f;
        #pragma unroll 8
        for (int c = 0; c < 64; c++) { float w = W[c]; vs += w * as[c]; vd += w * ad[c]; }
        g_vsrc[tid] = vs;
        g_vdst[tid] = vd;
    }
    if (tid < 32) {
        int h = tid >> 3, j = tid & 7;
        const float* We = conv_we + l * 2048 + j * 256 + h * 64;
        const float* ae = att_edge + l * 256 + h * 64;
        float we = 0.f;
        #pragma unroll 8
        for (int c = 0; c < 64; c++) we += We[c] * ae[c];
        g_wedge[tid] = we;
    }
}

// BN apply -> hn, plus per-node attention scores a_s, a_d
__global__ void k_bnapply() {
    __shared__ float sp[4][2][8];
    int c = threadIdx.x, ty = threadIdx.y;
    int n = blockIdx.x * 4 + ty;
    float hv = g_h[n * 64 + c] * g_scale[c] + g_shift[c];
    g_hn[n * 64 + c] = hv;
    float v[8];
    #pragma unroll
    for (int h = 0; h < 4; h++) {
        v[h]     = hv * g_vsrc[h * 64 + c];
        v[4 + h] = hv * g_vdst[h * 64 + c];
    }
    #pragma unroll
    for (int off = 16; off > 0; off >>= 1) {
        #pragma unroll
        for (int i = 0; i < 8; i++) v[i] += __shfl_down_sync(FULLM, v[i], off);
    }
    if ((c & 31) == 0) {
        #pragma unroll
        for (int i = 0; i < 8; i++) sp[ty][c >> 5][i] = v[i];
    }
    __syncthreads();
    if (c < 8) {
        float val = sp[ty][0][c] + sp[ty][1][c];
        if (c < 4) g_as[n * 4 + c] = val;
        else       g_ad[n * 4 + c - 4] = val;
    }
}

// edge score a_e
__global__ void k_aedge(const float* __restrict__ edge_attr) {
    __shared__ float we[32];
    int tid = threadIdx.x;
    if (tid < 32) we[tid] = g_wedge[tid];
    __syncthreads();
    int e = blockIdx.x * 256 + tid;
    if (e >= EE) return;
    float4 e0 = *(const float4*)(edge_attr + e * 8);
    float4 e1 = *(const float4*)(edge_attr + e * 8 + 4);
    float o[4];
    #pragma unroll
    for (int h = 0; h < 4; h++) {
        const float* w = &we[h * 8];
        o[h] = e0.x*w[0] + e0.y*w[1] + e0.z*w[2] + e0.w*w[3]
             + e1.x*w[4] + e1.y*w[5] + e1.z*w[6] + e1.w*w[7];
    }
    *(float4*)&g_ae[e * 4] = make_float4(o[0], o[1], o[2], o[3]);
}

__device__ __forceinline__ float lrelu(float a) { return a > 0.f ? a : 0.2f * a; }

// ---------------- fused conv (softmax-aggregate) + GEMM + bias/relu/skip ----
// 256 threads, 64 nodes per block.
// Phase A: 8 warps x 8 nodes each -> s[64][256] in smem (never touches DRAM).
// Phase B: per-head W slice staged in smem; thread tile 4 nodes x 4 channels,
//          packed fma.rn.f32x2 accumulators.
__global__ __launch_bounds__(256) void k_conv_gemm(
        int l, const int* __restrict__ ei,
        const float* __restrict__ conv_w,
        const float* __restrict__ conv_bias) {
    extern __shared__ float sm[];
    float* sSh = sm;             // 64*256 = 16384 floats
    float* wSh = sm + 16384;     // 64*64  = 4096 floats
    int tid = threadIdx.x;
    int wid = tid >> 5, lane = tid & 31;
    int nb = blockIdx.x * 64;

    // ---------- Phase A: attention softmax + aggregation ----------
    for (int jj = 0; jj < 8; jj++) {
        int nloc = (wid << 3) + jj;
        int n = nb + nloc;
        int start = g_rowstart[n];
        int end   = g_rowstart[n + 1];
        float4 ad4 = *(const float4*)&g_ad[n * 4];
        float m0 = -1e30f, m1 = -1e30f, m2 = -1e30f, m3 = -1e30f;
        for (int i = start + lane; i < end; i += 32) {
            int e = g_eid[i];
            int sv = ei[e];
            float4 as4 = *(const float4*)&g_as[sv * 4];
            float4 ae4 = *(const float4*)&g_ae[e * 4];
            m0 = fmaxf(m0, lrelu(as4.x + ad4.x + ae4.x));
            m1 = fmaxf(m1, lrelu(as4.y + ad4.y + ae4.y));
            m2 = fmaxf(m2, lrelu(as4.z + ad4.z + ae4.z));
            m3 = fmaxf(m3, lrelu(as4.w + ad4.w + ae4.w));
        }
        #pragma unroll
        for (int off = 16; off > 0; off >>= 1) {
            m0 = fmaxf(m0, __shfl_xor_sync(FULLM, m0, off));
            m1 = fmaxf(m1, __shfl_xor_sync(FULLM, m1, off));
            m2 = fmaxf(m2, __shfl_xor_sync(FULLM, m2, off));
            m3 = fmaxf(m3, __shfl_xor_sync(FULLM, m3, off));
        }
        float den0 = 0.f, den1 = 0.f, den2 = 0.f, den3 = 0.f;
        float aA0 = 0.f, aA1 = 0.f, aA2 = 0.f, aA3 = 0.f;
        float aB0 = 0.f, aB1 = 0.f, aB2 = 0.f, aB3 = 0.f;
        for (int i = start; i < end; i++) {
            int e = g_eid[i];
            int sv = ei[e];
            float4 as4 = *(const float4*)&g_as[sv * 4];
            float4 ae4 = *(const float4*)&g_ae[e * 4];
            float w0 = __expf(lrelu(as4.x + ad4.x + ae4.x) - m0);
            float w1 = __expf(lrelu(as4.y + ad4.y + ae4.y) - m1);
            float w2 = __expf(lrelu(as4.z + ad4.z + ae4.z) - m2);
            float w3 = __expf(lrelu(as4.w + ad4.w + ae4.w) - m3);
            den0 += w0; den1 += w1; den2 += w2; den3 += w3;
            float ha = g_hn[sv * 64 + lane];
            float hb = g_hn[sv * 64 + 32 + lane];
            aA0 = fmaf(w0, ha, aA0); aB0 = fmaf(w0, hb, aB0);
            aA1 = fmaf(w1, ha, aA1); aB1 = fmaf(w1, hb, aB1);
            aA2 = fmaf(w2, ha, aA2); aB2 = fmaf(w2, hb, aB2);
            aA3 = fmaf(w3, ha, aA3); aB3 = fmaf(w3, hb, aB3);
        }
        float i0 = 1.f / (den0 + 1e-16f);
        float i1 = 1.f / (den1 + 1e-16f);
        float i2 = 1.f / (den2 + 1e-16f);
        float i3 = 1.f / (den3 + 1e-16f);
        int base = nloc * 256 + lane;
        sSh[base +   0] = aA0 * i0;  sSh[base +  32] = aB0 * i0;
        sSh[base +  64] = aA1 * i1;  sSh[base +  96] = aB1 * i1;
        sSh[base + 128] = aA2 * i2;  sSh[base + 160] = aB2 * i2;
        sSh[base + 192] = aA3 * i3;  sSh[base + 224] = aB3 * i3;
    }

    // ---------- Phase B: projection GEMM ----------
    int cg = tid & 15;            // 4 channels
    int ng = tid >> 4;            // 4 nodes
    int c0 = cg * 4;
    unsigned long long acc[4][2];
    #pragma unroll
    for (int j = 0; j < 4; j++) { acc[j][0] = 0ULL; acc[j][1] = 0ULL; }

    const float* Wg = conv_w + l * 16384;
    for (int h = 0; h < 4; h++) {
        __syncthreads();
        // stage W[:, h*64 : (h+1)*64] -> wSh[64][64]
        for (int i = tid; i < 1024; i += 256) {
            int row = i >> 4, c4 = (i & 15) * 4;
            *(float4*)&wSh[row * 64 + c4] = *(const float4*)&Wg[row * 256 + h * 64 + c4];
        }
        __syncthreads();
        const float* sp = sSh + h * 64;
        #pragma unroll 4
        for (int k4 = 0; k4 < 16; k4++) {
            float4 s0 = *(const float4*)&sp[(ng * 4 + 0) * 256 + k4 * 4];
            float4 s1 = *(const float4*)&sp[(ng * 4 + 1) * 256 + k4 * 4];
            float4 s2 = *(const float4*)&sp[(ng * 4 + 2) * 256 + k4 * 4];
            float4 s3 = *(const float4*)&sp[(ng * 4 + 3) * 256 + k4 * 4];
            #pragma unroll
            for (int kk = 0; kk < 4; kk++) {
                float4 w = *(const float4*)&wSh[(k4 * 4 + kk) * 64 + c0];
                unsigned long long wlo = pk2(w.x, w.y);
                unsigned long long whi = pk2(w.z, w.w);
                float f0 = (kk == 0) ? s0.x : (kk == 1) ? s0.y : (kk == 2) ? s0.z : s0.w;
                float f1 = (kk == 0) ? s1.x : (kk == 1) ? s1.y : (kk == 2) ? s1.z : s1.w;
                float f2 = (kk == 0) ? s2.x : (kk == 1) ? s2.y : (kk == 2) ? s2.z : s2.w;
                float f3 = (kk == 0) ? s3.x : (kk == 1) ? s3.y : (kk == 2) ? s3.z : s3.w;
                unsigned long long p0 = pk2(f0, f0);
                unsigned long long p1 = pk2(f1, f1);
                unsigned long long p2 = pk2(f2, f2);
                unsigned long long p3 = pk2(f3, f3);
                fma2(acc[0][0], p0, wlo); fma2(acc[0][1], p0, whi);
                fma2(acc[1][0], p1, wlo); fma2(acc[1][1], p1, whi);
                fma2(acc[2][0], p2, wlo); fma2(acc[2][1], p2, whi);
                fma2(acc[3][0], p3, wlo); fma2(acc[3][1], p3, whi);
            }
        }
    }

    // epilogue: mean over heads, bias, relu, skip
    float4 bias4 = *(const float4*)&conv_bias[l * 64 + c0];
    #pragma unroll
    for (int j = 0; j < 4; j++) {
        int node = nb + ng * 4 + j;
        float2 lo = upk2(acc[j][0]);
        float2 hi = upk2(acc[j][1]);
        float4 old = *(const float4*)&g_h[node * 64 + c0];
        float4 o;
        o.x = fmaxf(lo.x * 0.25f + bias4.x, 0.0f) + old.x;
        o.y = fmaxf(lo.y * 0.25f + bias4.y, 0.0f) + old.y;
        o.z = fmaxf(hi.x * 0.25f + bias4.z, 0.0f) + old.z;
        o.w = fmaxf(hi.y * 0.25f + bias4.w, 0.0f) + old.w;
        *(float4*)&g_h[node * 64 + c0] = o;
    }
}

// ---------------- pooling + MLP head (fused, deterministic) ----------------
__device__ __forceinline__ int lower_bound_dev(const int* b, int n, int v) {
    int lo = 0, hi = n;
    while (lo < hi) {
        int mid = (lo + hi) >> 1;
        if (b[mid] < v) lo = mid + 1; else hi = mid;
    }
    return lo;
}

__global__ void k_pool_mlp(const int* __restrict__ batch,
                           const float* __restrict__ fc1_w,
                           const float* __restrict__ fc1_b,
                           const float* __restrict__ fc2_w,
                           const float* __restrict__ fc2_b,
                           float* __restrict__ out) {
    __shared__ float ps[64];
    __shared__ float r2[2];
    int g = blockIdx.x;
    int tid = threadIdx.x;
    int start = lower_bound_dev(batch, NN, g);
    int end   = lower_bound_dev(batch, NN, g + 1);
    float s = 0.f;
    for (int n = start; n < end; n++) s += g_h[n * 64 + tid];
    ps[tid] = s;
    __syncthreads();
    float z = fc1_b[tid];
    #pragma unroll 8
    for (int k = 0; k < 64; k++) z = fmaf(ps[k], fc1_w[k * 64 + tid], z);
    z = fmaxf(z, 0.0f);
    float p = z * fc2_w[tid];
    #pragma unroll
    for (int off = 16; off > 0; off >>= 1) p += __shfl_down_sync(FULLM, p, off);
    if ((tid & 31) == 0) r2[tid >> 5] = p;
    __syncthreads();
    if (tid == 0) out[g] = fmaxf(r2[0] + r2[1] + fc2_b[0], 0.0f);
}

// ---------------- launcher ----------------
extern "C" void kernel_launch(void* const* d_in, const int* in_sizes, int n_in,
                              void* d_out, int out_size) {
    const float* x         = (const float*)d_in[0];
    const int*   ei        = (const int*)  d_in[1];
    const float* edge_attr = (const float*)d_in[2];
    const int*   batch     = (const int*)  d_in[3];
    const float* lin_w     = (const float*)d_in[4];
    const float* lin_b     = (const float*)d_in[5];
    const float* bn_gamma  = (const float*)d_in[6];
    const float* bn_beta   = (const float*)d_in[7];
    const float* conv_w    = (const float*)d_in[8];
    const float* conv_we   = (const float*)d_in[9];
    const float* att_src   = (const float*)d_in[10];
    const float* att_dst   = (const float*)d_in[11];
    const float* att_edge  = (const float*)d_in[12];
    const float* conv_bias = (const float*)d_in[13];
    const float* fc1_w     = (const float*)d_in[14];
    const float* fc1_b     = (const float*)d_in[15];
    const float* fc2_w     = (const float*)d_in[16];
    const float* fc2_b     = (const float*)d_in[17];
    float* out = (float*)d_out;

    const int smem_cg = (16384 + 4096) * 4;   // 81920 B
    cudaFuncSetAttribute(k_conv_gemm, cudaFuncAttributeMaxDynamicSharedMemorySize, smem_cg);

    // CSR build (reused by all 3 layers)
    k_zero_deg<<<(NN + 255) / 256, 256>>>();
    k_degree<<<(EE + 255) / 256, 256>>>(ei);
    k_scan1<<<NB1, 1024>>>();
    k_scan2<<<1, 256>>>();
    k_scan3<<<NB1, 1024>>>();
    k_fill<<<(EE + 255) / 256, 256>>>(ei);

    // input projection
    k_lin<<<NN / 8, dim3(64, 8)>>>(x, lin_w, lin_b);

    for (int l = 0; l < 3; l++) {
        k_bnpart<<<NBP, dim3(64, 4)>>>();
        k_bnfin<<<1, 256>>>(l, bn_gamma, bn_beta, conv_w, conv_we,
                            att_src, att_dst, att_edge);
        k_bnapply<<<NN / 4, dim3(64, 4)>>>();
        k_aedge<<<(EE + 255) / 256, 256>>>(edge_attr);
        k_conv_gemm<<<NN / 64, 256, smem_cg>>>(l, ei, conv_w, conv_bias);
    }

    k_pool_mlp<<<GG, 64>>>(batch, fc1_w, fc1_b, fc2_w, fc2_b, out);
}

// round 4
// speedup vs baseline: 1.4015x; 1.0792x over previous
#include <cuda_runtime.h>
#include <cuda_fp16.h>
#include <math.h>

#define NN 200000
#define EE 400000
#define GG 8000
#define NBP 200           // batchnorm partial blocks
#define NB1 196           // scan blocks (196*1024 >= 200000)

// ---------------- device scratch ----------------
__device__ float  g_h [NN*64];
__device__ __half g_hnh[NN*64];
__device__ float  g_as[NN*4];
__device__ float  g_ad[NN*4];
__device__ float  g_sc[EE*4];
__device__ int    g_deg[NN];
__device__ int    g_rowstart[NN+1];
__device__ int    g_cursor[NN];
__device__ int    g_esrc[EE];
__device__ int    g_edst[EE];
__device__ int    g_eperm[EE];
__device__ int    g_tmpscan[NN];
__device__ int    g_bsum[256];
__device__ int    g_boff[256];
__device__ float  g_bnpart[NBP*128];
__device__ float  g_scale[64];
__device__ float  g_shift[64];
__device__ float  g_vsrc[256];
__device__ float  g_vdst[256];
__device__ float  g_wedge[32];

#define FULLM 0xffffffffu

// ---------------- f32x2 packed math helpers ----------------
__device__ __forceinline__ unsigned long long pk2(float a, float b) {
    unsigned long long r;
    asm("mov.b64 %0, {%1, %2};" : "=l"(r) : "f"(a), "f"(b));
    return r;
}
__device__ __forceinline__ void fma2(unsigned long long& d,
                                     unsigned long long a, unsigned long long b) {
    asm("fma.rn.f32x2 %0, %1, %2, %0;" : "+l"(d) : "l"(a), "l"(b));
}
__device__ __forceinline__ float2 upk2(unsigned long long v) {
    float2 r;
    asm("mov.b64 {%0, %1}, %2;" : "=f"(r.x), "=f"(r.y) : "l"(v));
    return r;
}

// ---------------- CSR build ----------------
__global__ void k_zero_deg() {
    int i = blockIdx.x * 256 + threadIdx.x;
    if (i < NN) g_deg[i] = 0;
}

__global__ void k_degree(const int* __restrict__ ei) {
    int e = blockIdx.x * 256 + threadIdx.x;
    if (e < EE) atomicAdd(&g_deg[ei[EE + e]], 1);
}

__global__ void k_scan1() {
    __shared__ int sh[1024];
    int tid = threadIdx.x;
    int t = blockIdx.x * 1024 + tid;
    int v = (t < NN) ? g_deg[t] : 0;
    sh[tid] = v;
    __syncthreads();
    for (int off = 1; off < 1024; off <<= 1) {
        int add = (tid >= off) ? sh[tid - off] : 0;
        __syncthreads();
        sh[tid] += add;
        __syncthreads();
    }
    if (t < NN) g_tmpscan[t] = sh[tid];
    if (tid == 1023) g_bsum[blockIdx.x] = sh[1023];
}

__global__ void k_scan2() {
    __shared__ int sh[256];
    int tid = threadIdx.x;
    int v = (tid < NB1) ? g_bsum[tid] : 0;
    sh[tid] = v;
    __syncthreads();
    for (int off = 1; off < 256; off <<= 1) {
        int add = (tid >= off) ? sh[tid - off] : 0;
        __syncthreads();
        sh[tid] += add;
        __syncthreads();
    }
    if (tid < NB1) g_boff[tid] = sh[tid] - v;   // exclusive
}

__global__ void k_scan3() {
    int tid = threadIdx.x;
    int t = blockIdx.x * 1024 + tid;
    if (t < NN) {
        int rs = g_boff[blockIdx.x] + g_tmpscan[t] - g_deg[t];
        g_rowstart[t] = rs;
        g_cursor[t] = rs;
    }
    if (t == 0) g_rowstart[NN] = EE;
}

__global__ void k_fill(const int* __restrict__ ei) {
    int e = blockIdx.x * 256 + threadIdx.x;
    if (e < EE) {
        int d = ei[EE + e];
        int s = ei[e];
        int p = atomicAdd(&g_cursor[d], 1);
        g_esrc[p] = s;
        g_edst[p] = d;
        g_eperm[p] = e;
    }
}

// ---------------- input projection ----------------
__global__ void k_lin(const float* __restrict__ x,
                      const float* __restrict__ lin_w,
                      const float* __restrict__ lin_b) {
    __shared__ float ws[2048];
    __shared__ float xt[8 * 32];
    int c = threadIdx.x;            // 0..63
    int r = threadIdx.y;            // 0..7
    int tid = c + r * 64;           // 0..511
    for (int i = tid; i < 2048; i += 512) ws[i] = lin_w[i];
    if (tid < 256) {
        int rr = tid >> 5, kk = tid & 31;
        xt[rr * 32 + kk] = x[(blockIdx.x * 8 + rr) * 32 + kk];
    }
    __syncthreads();
    float a = lin_b[c];
    #pragma unroll
    for (int k = 0; k < 32; k++) a = fmaf(xt[r * 32 + k], ws[k * 64 + c], a);
    g_h[(blockIdx.x * 8 + r) * 64 + c] = fmaxf(a, 0.0f);
}

// ---------------- batchnorm ----------------
__global__ void k_bnpart() {
    __shared__ float sh1[4][64];
    __shared__ float sh2[4][64];
    int c = threadIdx.x, ty = threadIdx.y;
    float s1 = 0.f, s2 = 0.f;
    for (int n = blockIdx.x * 4 + ty; n < NN; n += NBP * 4) {
        float v = g_h[n * 64 + c];
        s1 += v; s2 += v * v;
    }
    sh1[ty][c] = s1; sh2[ty][c] = s2;
    __syncthreads();
    if (ty == 0) {
        float t1 = sh1[0][c] + sh1[1][c] + sh1[2][c] + sh1[3][c];
        float t2 = sh2[0][c] + sh2[1][c] + sh2[2][c] + sh2[3][c];
        g_bnpart[blockIdx.x * 128 + c] = t1;
        g_bnpart[blockIdx.x * 128 + 64 + c] = t2;
    }
}

__global__ void k_bnfin(int l,
                        const float* __restrict__ gamma,
                        const float* __restrict__ beta,
                        const float* __restrict__ conv_w,
                        const float* __restrict__ conv_we,
                        const float* __restrict__ att_src,
                        const float* __restrict__ att_dst,
                        const float* __restrict__ att_edge) {
    int tid = threadIdx.x;
    if (tid < 64) {
        float s1 = 0.f, s2 = 0.f;
        for (int b = 0; b < NBP; b++) {
            s1 += g_bnpart[b * 128 + tid];
            s2 += g_bnpart[b * 128 + 64 + tid];
        }
        float mu = s1 / (float)NN;
        float var = s2 / (float)NN - mu * mu;
        float sc = gamma[l * 64 + tid] * rsqrtf(var + 1e-5f);
        g_scale[tid] = sc;
        g_shift[tid] = beta[l * 64 + tid] - mu * sc;
    }
    // fold attention vectors: v_src[h][k] = sum_c W[k][h*64+c]*att_src[h][c]
    {
        int h = tid >> 6, k = tid & 63;
        const float* W = conv_w + l * 16384 + k * 256 + h * 64;
        const float* as = att_src + l * 256 + h * 64;
        const float* ad = att_dst + l * 256 + h * 64;
        float vs = 0.f, vd = 0.f;
        #pragma unroll 8
        for (int c = 0; c < 64; c++) { float w = W[c]; vs += w * as[c]; vd += w * ad[c]; }
        g_vsrc[tid] = vs;
        g_vdst[tid] = vd;
    }
    if (tid < 32) {
        int h = tid >> 3, j = tid & 7;
        const float* We = conv_we + l * 2048 + j * 256 + h * 64;
        const float* ae = att_edge + l * 256 + h * 64;
        float we = 0.f;
        #pragma unroll 8
        for (int c = 0; c < 64; c++) we += We[c] * ae[c];
        g_wedge[tid] = we;
    }
}

// BN apply -> hnh (fp16), plus per-node attention scores a_s, a_d
__global__ void k_bnapply() {
    __shared__ float sp[4][2][8];
    int c = threadIdx.x, ty = threadIdx.y;
    int n = blockIdx.x * 4 + ty;
    float hv = g_h[n * 64 + c] * g_scale[c] + g_shift[c];
    g_hnh[n * 64 + c] = __float2half_rn(hv);
    float v[8];
    #pragma unroll
    for (int h = 0; h < 4; h++) {
        v[h]     = hv * g_vsrc[h * 64 + c];
        v[4 + h] = hv * g_vdst[h * 64 + c];
    }
    #pragma unroll
    for (int off = 16; off > 0; off >>= 1) {
        #pragma unroll
        for (int i = 0; i < 8; i++) v[i] += __shfl_down_sync(FULLM, v[i], off);
    }
    if ((c & 31) == 0) {
        #pragma unroll
        for (int i = 0; i < 8; i++) sp[ty][c >> 5][i] = v[i];
    }
    __syncthreads();
    if (c < 8) {
        float val = sp[ty][0][c] + sp[ty][1][c];
        if (c < 4) g_as[n * 4 + c] = val;
        else       g_ad[n * 4 + c - 4] = val;
    }
}

__device__ __forceinline__ float lrelu(float a) { return a > 0.f ? a : 0.2f * a; }

// edge scores in CSR position order: sc[p] = lrelu(a_s[src] + a_d[dst] + a_e)
__global__ void k_escore(const float* __restrict__ edge_attr) {
    __shared__ float we[32];
    int tid = threadIdx.x;
    if (tid < 32) we[tid] = g_wedge[tid];
    __syncthreads();
    int p = blockIdx.x * 256 + tid;
    if (p >= EE) return;
    int e  = g_eperm[p];
    int sv = g_esrc[p];
    int dv = g_edst[p];
    float4 as4 = *(const float4*)&g_as[sv * 4];
    float4 ad4 = *(const float4*)&g_ad[dv * 4];
    float4 e0 = *(const float4*)(edge_attr + e * 8);
    float4 e1 = *(const float4*)(edge_attr + e * 8 + 4);
    float ax[4] = {as4.x + ad4.x, as4.y + ad4.y, as4.z + ad4.z, as4.w + ad4.w};
    float o[4];
    #pragma unroll
    for (int h = 0; h < 4; h++) {
        const float* w = &we[h * 8];
        float ae = e0.x*w[0] + e0.y*w[1] + e0.z*w[2] + e0.w*w[3]
                 + e1.x*w[4] + e1.y*w[5] + e1.z*w[6] + e1.w*w[7];
        o[h] = lrelu(ax[h] + ae);
    }
    *(float4*)&g_sc[p * 4] = make_float4(o[0], o[1], o[2], o[3]);
}

// ---------------- fused conv (softmax-aggregate) + GEMM + bias/relu/skip ----
// 256 threads, 32 nodes per block, 4 blocks/SM.
// Phase A: 8 warps x 4 nodes; scores coalesced from g_sc, hn gathered as fp16.
// Phase B: per-head W slice staged in smem; thread tile 2 nodes x 4 channels,
//          packed fma.rn.f32x2 accumulators.
__global__ __launch_bounds__(256, 4) void k_conv_gemm(
        int l,
        const float* __restrict__ conv_w,
        const float* __restrict__ conv_bias) {
    extern __shared__ float sm[];
    float* sSh = sm;             // 32*256 = 8192 floats
    float* wSh = sm + 8192;      // 64*64  = 4096 floats
    int tid = threadIdx.x;
    int wid = tid >> 5, lane = tid & 31;
    int nb = blockIdx.x * 32;

    // ---------- Phase A: attention softmax + aggregation ----------
    for (int jj = 0; jj < 4; jj++) {
        int nloc = (wid << 2) + jj;
        int n = nb + nloc;
        int start = g_rowstart[n];
        int end   = g_rowstart[n + 1];
        // pass 1: max over scores (coalesced, lane-strided)
        float m0 = -1e30f, m1 = -1e30f, m2 = -1e30f, m3 = -1e30f;
        for (int i = start + lane; i < end; i += 32) {
            float4 sc = *(const float4*)&g_sc[i * 4];
            m0 = fmaxf(m0, sc.x); m1 = fmaxf(m1, sc.y);
            m2 = fmaxf(m2, sc.z); m3 = fmaxf(m3, sc.w);
        }
        #pragma unroll
        for (int off = 16; off > 0; off >>= 1) {
            m0 = fmaxf(m0, __shfl_xor_sync(FULLM, m0, off));
            m1 = fmaxf(m1, __shfl_xor_sync(FULLM, m1, off));
            m2 = fmaxf(m2, __shfl_xor_sync(FULLM, m2, off));
            m3 = fmaxf(m3, __shfl_xor_sync(FULLM, m3, off));
        }
        // pass 2: exp weights + fp16 hn aggregation (channels 2*lane, 2*lane+1)
        float den0 = 0.f, den1 = 0.f, den2 = 0.f, den3 = 0.f;
        float aA0 = 0.f, aA1 = 0.f, aA2 = 0.f, aA3 = 0.f;
        float aB0 = 0.f, aB1 = 0.f, aB2 = 0.f, aB3 = 0.f;
        for (int i = start; i < end; i++) {
            float4 sc = *(const float4*)&g_sc[i * 4];
            int sv = g_esrc[i];
            float w0 = __expf(sc.x - m0);
            float w1 = __expf(sc.y - m1);
            float w2 = __expf(sc.z - m2);
            float w3 = __expf(sc.w - m3);
            den0 += w0; den1 += w1; den2 += w2; den3 += w3;
            __half2 hh = ((const __half2*)g_hnh)[sv * 32 + lane];
            float2 hf = __half22float2(hh);
            aA0 = fmaf(w0, hf.x, aA0); aB0 = fmaf(w0, hf.y, aB0);
            aA1 = fmaf(w1, hf.x, aA1); aB1 = fmaf(w1, hf.y, aB1);
            aA2 = fmaf(w2, hf.x, aA2); aB2 = fmaf(w2, hf.y, aB2);
            aA3 = fmaf(w3, hf.x, aA3); aB3 = fmaf(w3, hf.y, aB3);
        }
        float i0 = 1.f / (den0 + 1e-16f);
        float i1 = 1.f / (den1 + 1e-16f);
        float i2 = 1.f / (den2 + 1e-16f);
        float i3 = 1.f / (den3 + 1e-16f);
        int base = nloc * 256 + 2 * lane;
        *(float2*)&sSh[base +   0] = make_float2(aA0 * i0, aB0 * i0);
        *(float2*)&sSh[base +  64] = make_float2(aA1 * i1, aB1 * i1);
        *(float2*)&sSh[base + 128] = make_float2(aA2 * i2, aB2 * i2);
        *(float2*)&sSh[base + 192] = make_float2(aA3 * i3, aB3 * i3);
    }

    // ---------- Phase B: projection GEMM ----------
    int cg = tid & 15;            // 4 channels
    int ng = tid >> 4;            // 2 nodes (0..15)
    int c0 = cg * 4;
    unsigned long long acc[2][2];
    acc[0][0] = 0ULL; acc[0][1] = 0ULL; acc[1][0] = 0ULL; acc[1][1] = 0ULL;

    const float* Wg = conv_w + l * 16384;
    for (int h = 0; h < 4; h++) {
        __syncthreads();
        // stage W[:, h*64 : (h+1)*64] -> wSh[64][64]
        for (int i = tid; i < 1024; i += 256) {
            int row = i >> 4, c4 = (i & 15) * 4;
            *(float4*)&wSh[row * 64 + c4] = *(const float4*)&Wg[row * 256 + h * 64 + c4];
        }
        __syncthreads();
        const float* sp = sSh + h * 64;
        #pragma unroll 4
        for (int k4 = 0; k4 < 16; k4++) {
            float4 s0 = *(const float4*)&sp[(ng * 2 + 0) * 256 + k4 * 4];
            float4 s1 = *(const float4*)&sp[(ng * 2 + 1) * 256 + k4 * 4];
            #pragma unroll
            for (int kk = 0; kk < 4; kk++) {
                float4 w = *(const float4*)&wSh[(k4 * 4 + kk) * 64 + c0];
                unsigned long long wlo = pk2(w.x, w.y);
                unsigned long long whi = pk2(w.z, w.w);
                float f0 = (kk == 0) ? s0.x : (kk == 1) ? s0.y : (kk == 2) ? s0.z : s0.w;
                float f1 = (kk == 0) ? s1.x : (kk == 1) ? s1.y : (kk == 2) ? s1.z : s1.w;
                unsigned long long p0 = pk2(f0, f0);
                unsigned long long p1 = pk2(f1, f1);
                fma2(acc[0][0], p0, wlo); fma2(acc[0][1], p0, whi);
                fma2(acc[1][0], p1, wlo); fma2(acc[1][1], p1, whi);
            }
        }
    }

    // epilogue: mean over heads, bias, relu, skip
    float4 bias4 = *(const float4*)&conv_bias[l * 64 + c0];
    #pragma unroll
    for (int j = 0; j < 2; j++) {
        int node = nb + ng * 2 + j;
        float2 lo = upk2(acc[j][0]);
        float2 hi = upk2(acc[j][1]);
        float4 old = *(const float4*)&g_h[node * 64 + c0];
        float4 o;
        o.x = fmaxf(lo.x * 0.25f + bias4.x, 0.0f) + old.x;
        o.y = fmaxf(lo.y * 0.25f + bias4.y, 0.0f) + old.y;
        o.z = fmaxf(hi.x * 0.25f + bias4.z, 0.0f) + old.z;
        o.w = fmaxf(hi.y * 0.25f + bias4.w, 0.0f) + old.w;
        *(float4*)&g_h[node * 64 + c0] = o;
    }
}

// ---------------- pooling + MLP head (fused, deterministic) ----------------
__device__ __forceinline__ int lower_bound_dev(const int* b, int n, int v) {
    int lo = 0, hi = n;
    while (lo < hi) {
        int mid = (lo + hi) >> 1;
        if (b[mid] < v) lo = mid + 1; else hi = mid;
    }
    return lo;
}

__global__ void k_pool_mlp(const int* __restrict__ batch,
                           const float* __restrict__ fc1_w,
                           const float* __restrict__ fc1_b,
                           const float* __restrict__ fc2_w,
                           const float* __restrict__ fc2_b,
                           float* __restrict__ out) {
    __shared__ float ps[64];
    __shared__ float r2[2];
    int g = blockIdx.x;
    int tid = threadIdx.x;
    int start = lower_bound_dev(batch, NN, g);
    int end   = lower_bound_dev(batch, NN, g + 1);
    float s = 0.f;
    for (int n = start; n < end; n++) s += g_h[n * 64 + tid];
    ps[tid] = s;
    __syncthreads();
    float z = fc1_b[tid];
    #pragma unroll 8
    for (int k = 0; k < 64; k++) z = fmaf(ps[k], fc1_w[k * 64 + tid], z);
    z = fmaxf(z, 0.0f);
    float p = z * fc2_w[tid];
    #pragma unroll
    for (int off = 16; off > 0; off >>= 1) p += __shfl_down_sync(FULLM, p, off);
    if ((tid & 31) == 0) r2[tid >> 5] = p;
    __syncthreads();
    if (tid == 0) out[g] = fmaxf(r2[0] + r2[1] + fc2_b[0], 0.0f);
}

// ---------------- launcher ----------------
extern "C" void kernel_launch(void* const* d_in, const int* in_sizes, int n_in,
                              void* d_out, int out_size) {
    const float* x         = (const float*)d_in[0];
    const int*   ei        = (const int*)  d_in[1];
    const float* edge_attr = (const float*)d_in[2];
    const int*   batch     = (const int*)  d_in[3];
    const float* lin_w     = (const float*)d_in[4];
    const float* lin_b     = (const float*)d_in[5];
    const float* bn_gamma  = (const float*)d_in[6];
    const float* bn_beta   = (const float*)d_in[7];
    const float* conv_w    = (const float*)d_in[8];
    const float* conv_we   = (const float*)d_in[9];
    const float* att_src   = (const float*)d_in[10];
    const float* att_dst   = (const float*)d_in[11];
    const float* att_edge  = (const float*)d_in[12];
    const float* conv_bias = (const float*)d_in[13];
    const float* fc1_w     = (const float*)d_in[14];
    const float* fc1_b     = (const float*)d_in[15];
    const float* fc2_w     = (const float*)d_in[16];
    const float* fc2_b     = (const float*)d_in[17];
    float* out = (float*)d_out;

    const int smem_cg = (8192 + 4096) * 4;   // 49152 B
    cudaFuncSetAttribute(k_conv_gemm, cudaFuncAttributeMaxDynamicSharedMemorySize, smem_cg);

    // CSR build (reused by all 3 layers)
    k_zero_deg<<<(NN + 255) / 256, 256>>>();
    k_degree<<<(EE + 255) / 256, 256>>>(ei);
    k_scan1<<<NB1, 1024>>>();
    k_scan2<<<1, 256>>>();
    k_scan3<<<NB1, 1024>>>();
    k_fill<<<(EE + 255) / 256, 256>>>(ei);

    // input projection
    k_lin<<<NN / 8, dim3(64, 8)>>>(x, lin_w, lin_b);

    for (int l = 0; l < 3; l++) {
        k_bnpart<<<NBP, dim3(64, 4)>>>();
        k_bnfin<<<1, 256>>>(l, bn_gamma, bn_beta, conv_w, conv_we,
                            att_src, att_dst, att_edge);
        k_bnapply<<<NN / 4, dim3(64, 4)>>>();
        k_escore<<<(EE + 255) / 256, 256>>>(edge_attr);
        k_conv_gemm<<<NN / 32, 256, smem_cg>>>(l, conv_w, conv_bias);
    }

    k_pool_mlp<<<GG, 64>>>(batch, fc1_w, fc1_b, fc2_w, fc2_b, out);
}

// round 5
// speedup vs baseline: 1.5875x; 1.1327x over previous
#include <cuda_runtime.h>
#include <cuda_fp16.h>
#include <math.h>

#define NN 200000
#define EE 400000
#define GG 8000
#define NB1 196           // scan blocks (196*1024 >= 200000)
#define NSLOT 64          // bn accumulator slots (contention spreading)

// ---------------- device scratch ----------------
__device__ float    g_h [NN*64];
__device__ __half   g_hnh[NN*64];
__device__ float    g_as[NN*4];
__device__ float    g_ad[NN*4];
__device__ float    g_sc[EE*4];
__device__ int      g_deg[NN];
__device__ int      g_rowstart[NN+1];
__device__ int      g_cursor[NN];
__device__ int      g_esrc[EE];
__device__ int      g_edst[EE];
__device__ int      g_eperm[EE];
__device__ int      g_tmpscan[NN];
__device__ int      g_bsum[256];
__device__ int      g_boff[256];
__device__ float    g_bnacc[3][NSLOT][128];   // [layer][slot][sum(64) | sumsq(64)]
__device__ unsigned g_gmaxu[4];               // per-head global score max (ordered-uint)
__device__ float    g_scale[64];
__device__ float    g_shift[64];
__device__ float    g_vsrc[256];
__device__ float    g_vdst[256];
__device__ float    g_wedge[32];

#define FULLM 0xffffffffu

// ordered-uint encoding for float atomicMax (monotone increasing)
__device__ __forceinline__ unsigned encf(float f) {
    unsigned u = __float_as_uint(f);
    return (u & 0x80000000u) ? ~u : (u | 0x80000000u);
}
__device__ __forceinline__ float decf(unsigned u) {
    return (u & 0x80000000u) ? __uint_as_float(u & 0x7fffffffu)
                             : __uint_as_float(~u);
}

// ---------------- f32x2 packed math helpers ----------------
__device__ __forceinline__ unsigned long long pk2(float a, float b) {
    unsigned long long r;
    asm("mov.b64 %0, {%1, %2};" : "=l"(r) : "f"(a), "f"(b));
    return r;
}
__device__ __forceinline__ void fma2(unsigned long long& d,
                                     unsigned long long a, unsigned long long b) {
    asm("fma.rn.f32x2 %0, %1, %2, %0;" : "+l"(d) : "l"(a), "l"(b));
}
__device__ __forceinline__ float2 upk2(unsigned long long v) {
    float2 r;
    asm("mov.b64 {%0, %1}, %2;" : "=f"(r.x), "=f"(r.y) : "l"(v));
    return r;
}

// ---------------- zero scratch (deg + bn accumulators) ----------------
__global__ void k_zero() {
    int i = blockIdx.x * 256 + threadIdx.x;
    if (i < NN) g_deg[i] = 0;
    if (i < 3 * NSLOT * 128) ((float*)g_bnacc)[i] = 0.0f;
}

__global__ void k_degree(const int* __restrict__ ei) {
    int e = blockIdx.x * 256 + threadIdx.x;
    if (e < EE) atomicAdd(&g_deg[ei[EE + e]], 1);
}

__global__ void k_scan1() {
    __shared__ int sh[1024];
    int tid = threadIdx.x;
    int t = blockIdx.x * 1024 + tid;
    int v = (t < NN) ? g_deg[t] : 0;
    sh[tid] = v;
    __syncthreads();
    for (int off = 1; off < 1024; off <<= 1) {
        int add = (tid >= off) ? sh[tid - off] : 0;
        __syncthreads();
        sh[tid] += add;
        __syncthreads();
    }
    if (t < NN) g_tmpscan[t] = sh[tid];
    if (tid == 1023) g_bsum[blockIdx.x] = sh[1023];
}

__global__ void k_scan2() {
    __shared__ int sh[256];
    int tid = threadIdx.x;
    int v = (tid < NB1) ? g_bsum[tid] : 0;
    sh[tid] = v;
    __syncthreads();
    for (int off = 1; off < 256; off <<= 1) {
        int add = (tid >= off) ? sh[tid - off] : 0;
        __syncthreads();
        sh[tid] += add;
        __syncthreads();
    }
    if (tid < NB1) g_boff[tid] = sh[tid] - v;   // exclusive
}

__global__ void k_scan3() {
    int tid = threadIdx.x;
    int t = blockIdx.x * 1024 + tid;
    if (t < NN) {
        int rs = g_boff[blockIdx.x] + g_tmpscan[t] - g_deg[t];
        g_rowstart[t] = rs;
        g_cursor[t] = rs;
    }
    if (t == 0) g_rowstart[NN] = EE;
}

__global__ void k_fill(const int* __restrict__ ei) {
    int e = blockIdx.x * 256 + threadIdx.x;
    if (e < EE) {
        int d = ei[EE + e];
        int s = ei[e];
        int p = atomicAdd(&g_cursor[d], 1);
        g_esrc[p] = s;
        g_edst[p] = d;
        g_eperm[p] = e;
    }
}

// ---------------- input projection (+ BN stats for layer 0) ----------------
__global__ void k_lin(const float* __restrict__ x,
                      const float* __restrict__ lin_w,
                      const float* __restrict__ lin_b) {
    __shared__ float ws[2048];
    __shared__ float xt[8 * 32];
    int c = threadIdx.x;            // 0..63
    int r = threadIdx.y;            // 0..7
    int tid = c + r * 64;           // 0..511
    for (int i = tid; i < 2048; i += 512) ws[i] = lin_w[i];
    if (tid < 256) {
        int rr = tid >> 5, kk = tid & 31;
        xt[rr * 32 + kk] = x[(blockIdx.x * 8 + rr) * 32 + kk];
    }
    __syncthreads();
    float a = lin_b[c];
    #pragma unroll
    for (int k = 0; k < 32; k++) a = fmaf(xt[r * 32 + k], ws[k * 64 + c], a);
    a = fmaxf(a, 0.0f);
    g_h[(blockIdx.x * 8 + r) * 64 + c] = a;
    // BN stats for layer 0 (reuse ws after sync)
    __syncthreads();
    ws[r * 64 + c] = a;
    __syncthreads();
    if (r == 0) {
        float s1 = 0.f, s2 = 0.f;
        #pragma unroll
        for (int rr = 0; rr < 8; rr++) {
            float v = ws[rr * 64 + c];
            s1 += v; s2 += v * v;
        }
        int slot = blockIdx.x & (NSLOT - 1);
        atomicAdd(&g_bnacc[0][slot][c], s1);
        atomicAdd(&g_bnacc[0][slot][64 + c], s2);
    }
}

// ---------------- bn finalize + fold attention vectors + reset gmax ------
__global__ void k_bnfin(int l,
                        const float* __restrict__ gamma,
                        const float* __restrict__ beta,
                        const float* __restrict__ conv_w,
                        const float* __restrict__ conv_we,
                        const float* __restrict__ att_src,
                        const float* __restrict__ att_dst,
                        const float* __restrict__ att_edge) {
    int tid = threadIdx.x;
    if (tid < 64) {
        float s1 = 0.f, s2 = 0.f;
        for (int b = 0; b < NSLOT; b++) {
            s1 += g_bnacc[l][b][tid];
            s2 += g_bnacc[l][b][64 + tid];
        }
        float mu = s1 / (float)NN;
        float var = s2 / (float)NN - mu * mu;
        float sc = gamma[l * 64 + tid] * rsqrtf(var + 1e-5f);
        g_scale[tid] = sc;
        g_shift[tid] = beta[l * 64 + tid] - mu * sc;
    }
    if (tid < 4) g_gmaxu[tid] = encf(-1e30f);
    // fold attention vectors: v_src[h][k] = sum_c W[k][h*64+c]*att_src[h][c]
    {
        int h = tid >> 6, k = tid & 63;
        const float* W = conv_w + l * 16384 + k * 256 + h * 64;
        const float* as = att_src + l * 256 + h * 64;
        const float* ad = att_dst + l * 256 + h * 64;
        float vs = 0.f, vd = 0.f;
        #pragma unroll 8
        for (int c = 0; c < 64; c++) { float w = W[c]; vs += w * as[c]; vd += w * ad[c]; }
        g_vsrc[tid] = vs;
        g_vdst[tid] = vd;
    }
    if (tid < 32) {
        int h = tid >> 3, j = tid & 7;
        const float* We = conv_we + l * 2048 + j * 256 + h * 64;
        const float* ae = att_edge + l * 256 + h * 64;
        float we = 0.f;
        #pragma unroll 8
        for (int c = 0; c < 64; c++) we += We[c] * ae[c];
        g_wedge[tid] = we;
    }
}

// BN apply -> hnh (fp16), plus per-node attention scores a_s, a_d
__global__ void k_bnapply() {
    __shared__ float sp[4][2][8];
    int c = threadIdx.x, ty = threadIdx.y;
    int n = blockIdx.x * 4 + ty;
    float hv = g_h[n * 64 + c] * g_scale[c] + g_shift[c];
    g_hnh[n * 64 + c] = __float2half_rn(hv);
    float v[8];
    #pragma unroll
    for (int h = 0; h < 4; h++) {
        v[h]     = hv * g_vsrc[h * 64 + c];
        v[4 + h] = hv * g_vdst[h * 64 + c];
    }
    #pragma unroll
    for (int off = 16; off > 0; off >>= 1) {
        #pragma unroll
        for (int i = 0; i < 8; i++) v[i] += __shfl_down_sync(FULLM, v[i], off);
    }
    if ((c & 31) == 0) {
        #pragma unroll
        for (int i = 0; i < 8; i++) sp[ty][c >> 5][i] = v[i];
    }
    __syncthreads();
    if (c < 8) {
        float val = sp[ty][0][c] + sp[ty][1][c];
        if (c < 4) g_as[n * 4 + c] = val;
        else       g_ad[n * 4 + c - 4] = val;
    }
}

__device__ __forceinline__ float lrelu(float a) { return a > 0.f ? a : 0.2f * a; }

// edge scores in CSR order + per-head global max (for safe exp shift)
__global__ void k_escore(const float* __restrict__ edge_attr) {
    __shared__ float we[32];
    __shared__ float red[8][4];
    int tid = threadIdx.x;
    if (tid < 32) we[tid] = g_wedge[tid];
    __syncthreads();
    int p = blockIdx.x * 256 + tid;
    float o[4] = {-1e30f, -1e30f, -1e30f, -1e30f};
    if (p < EE) {
        int e  = g_eperm[p];
        int sv = g_esrc[p];
        int dv = g_edst[p];
        float4 as4 = *(const float4*)&g_as[sv * 4];
        float4 ad4 = *(const float4*)&g_ad[dv * 4];
        float4 e0 = *(const float4*)(edge_attr + e * 8);
        float4 e1 = *(const float4*)(edge_attr + e * 8 + 4);
        float ax[4] = {as4.x + ad4.x, as4.y + ad4.y, as4.z + ad4.z, as4.w + ad4.w};
        #pragma unroll
        for (int h = 0; h < 4; h++) {
            const float* w = &we[h * 8];
            float ae = e0.x*w[0] + e0.y*w[1] + e0.z*w[2] + e0.w*w[3]
                     + e1.x*w[4] + e1.y*w[5] + e1.z*w[6] + e1.w*w[7];
            o[h] = lrelu(ax[h] + ae);
        }
        *(float4*)&g_sc[p * 4] = make_float4(o[0], o[1], o[2], o[3]);
    }
    // block max -> global atomicMax (4 per block)
    float m[4] = {o[0], o[1], o[2], o[3]};
    #pragma unroll
    for (int off = 16; off > 0; off >>= 1) {
        #pragma unroll
        for (int h = 0; h < 4; h++)
            m[h] = fmaxf(m[h], __shfl_xor_sync(FULLM, m[h], off));
    }
    if ((tid & 31) == 0) {
        #pragma unroll
        for (int h = 0; h < 4; h++) red[tid >> 5][h] = m[h];
    }
    __syncthreads();
    if (tid < 4) {
        float mm = red[0][tid];
        #pragma unroll
        for (int wg = 1; wg < 8; wg++) mm = fmaxf(mm, red[wg][tid]);
        atomicMax(&g_gmaxu[tid], encf(mm));
    }
}

// ---------------- fused conv + GEMM + bias/relu/skip + BN stats ----------
// 256 threads, 32 nodes per block, 4 blocks/SM.
// Phase A: SINGLE pass — w = exp(sc - gmax_h) inline (softmax shift-invariant).
// Phase B: per-head W slice staged in smem; packed fma.rn.f32x2.
// Epilogue: BN statistics for layer l+1 accumulated via slot atomics.
__global__ __launch_bounds__(256, 4) void k_conv_gemm(
        int l,
        const float* __restrict__ conv_w,
        const float* __restrict__ conv_bias) {
    extern __shared__ float sm[];
    float* sSh = sm;             // 32*256 = 8192 floats
    float* wSh = sm + 8192;      // 64*64  = 4096 floats
    int tid = threadIdx.x;
    int wid = tid >> 5, lane = tid & 31;
    int nb = blockIdx.x * 32;

    float gm0 = decf(g_gmaxu[0]);
    float gm1 = decf(g_gmaxu[1]);
    float gm2 = decf(g_gmaxu[2]);
    float gm3 = decf(g_gmaxu[3]);

    // ---------- Phase A: single-pass softmax + aggregation ----------
    for (int jj = 0; jj < 4; jj++) {
        int nloc = (wid << 2) + jj;
        int n = nb + nloc;
        int start = g_rowstart[n];
        int end   = g_rowstart[n + 1];
        float den0 = 0.f, den1 = 0.f, den2 = 0.f, den3 = 0.f;
        float aA0 = 0.f, aA1 = 0.f, aA2 = 0.f, aA3 = 0.f;
        float aB0 = 0.f, aB1 = 0.f, aB2 = 0.f, aB3 = 0.f;
        for (int i = start; i < end; i++) {
            float4 sc = *(const float4*)&g_sc[i * 4];
            int sv = g_esrc[i];
            float w0 = __expf(sc.x - gm0);
            float w1 = __expf(sc.y - gm1);
            float w2 = __expf(sc.z - gm2);
            float w3 = __expf(sc.w - gm3);
            den0 += w0; den1 += w1; den2 += w2; den3 += w3;
            __half2 hh = ((const __half2*)g_hnh)[sv * 32 + lane];
            float2 hf = __half22float2(hh);
            aA0 = fmaf(w0, hf.x, aA0); aB0 = fmaf(w0, hf.y, aB0);
            aA1 = fmaf(w1, hf.x, aA1); aB1 = fmaf(w1, hf.y, aB1);
            aA2 = fmaf(w2, hf.x, aA2); aB2 = fmaf(w2, hf.y, aB2);
            aA3 = fmaf(w3, hf.x, aA3); aB3 = fmaf(w3, hf.y, aB3);
        }
        float i0 = 1.f / (den0 + 1e-16f);
        float i1 = 1.f / (den1 + 1e-16f);
        float i2 = 1.f / (den2 + 1e-16f);
        float i3 = 1.f / (den3 + 1e-16f);
        int base = nloc * 256 + 2 * lane;
        *(float2*)&sSh[base +   0] = make_float2(aA0 * i0, aB0 * i0);
        *(float2*)&sSh[base +  64] = make_float2(aA1 * i1, aB1 * i1);
        *(float2*)&sSh[base + 128] = make_float2(aA2 * i2, aB2 * i2);
        *(float2*)&sSh[base + 192] = make_float2(aA3 * i3, aB3 * i3);
    }

    // ---------- Phase B: projection GEMM ----------
    int cg = tid & 15;            // 4 channels
    int ng = tid >> 4;            // 2 nodes (0..15)
    int c0 = cg * 4;
    unsigned long long acc[2][2];
    acc[0][0] = 0ULL; acc[0][1] = 0ULL; acc[1][0] = 0ULL; acc[1][1] = 0ULL;

    const float* Wg = conv_w + l * 16384;
    for (int h = 0; h < 4; h++) {
        __syncthreads();
        for (int i = tid; i < 1024; i += 256) {
            int row = i >> 4, c4 = (i & 15) * 4;
            *(float4*)&wSh[row * 64 + c4] = *(const float4*)&Wg[row * 256 + h * 64 + c4];
        }
        __syncthreads();
        const float* sp = sSh + h * 64;
        #pragma unroll 4
        for (int k4 = 0; k4 < 16; k4++) {
            float4 s0 = *(const float4*)&sp[(ng * 2 + 0) * 256 + k4 * 4];
            float4 s1 = *(const float4*)&sp[(ng * 2 + 1) * 256 + k4 * 4];
            #pragma unroll
            for (int kk = 0; kk < 4; kk++) {
                float4 w = *(const float4*)&wSh[(k4 * 4 + kk) * 64 + c0];
                unsigned long long wlo = pk2(w.x, w.y);
                unsigned long long whi = pk2(w.z, w.w);
                float f0 = (kk == 0) ? s0.x : (kk == 1) ? s0.y : (kk == 2) ? s0.z : s0.w;
                float f1 = (kk == 0) ? s1.x : (kk == 1) ? s1.y : (kk == 2) ? s1.z : s1.w;
                unsigned long long p0 = pk2(f0, f0);
                unsigned long long p1 = pk2(f1, f1);
                fma2(acc[0][0], p0, wlo); fma2(acc[0][1], p0, whi);
                fma2(acc[1][0], p1, wlo); fma2(acc[1][1], p1, whi);
            }
        }
    }

    // epilogue: mean over heads, bias, relu, skip; collect BN stats
    float4 bias4 = *(const float4*)&conv_bias[l * 64 + c0];
    float bs1[4] = {0.f, 0.f, 0.f, 0.f};
    float bs2[4] = {0.f, 0.f, 0.f, 0.f};
    #pragma unroll
    for (int j = 0; j < 2; j++) {
        int node = nb + ng * 2 + j;
        float2 lo = upk2(acc[j][0]);
        float2 hi = upk2(acc[j][1]);
        float4 old = *(const float4*)&g_h[node * 64 + c0];
        float4 o;
        o.x = fmaxf(lo.x * 0.25f + bias4.x, 0.0f) + old.x;
        o.y = fmaxf(lo.y * 0.25f + bias4.y, 0.0f) + old.y;
        o.z = fmaxf(hi.x * 0.25f + bias4.z, 0.0f) + old.z;
        o.w = fmaxf(hi.y * 0.25f + bias4.w, 0.0f) + old.w;
        *(float4*)&g_h[node * 64 + c0] = o;
        bs1[0] += o.x; bs1[1] += o.y; bs1[2] += o.z; bs1[3] += o.w;
        bs2[0] += o.x*o.x; bs2[1] += o.y*o.y; bs2[2] += o.z*o.z; bs2[3] += o.w*o.w;
    }
    if (l < 2) {
        __syncthreads();
        *(float4*)&sSh[ng * 128 + c0]      = make_float4(bs1[0], bs1[1], bs1[2], bs1[3]);
        *(float4*)&sSh[ng * 128 + 64 + c0] = make_float4(bs2[0], bs2[1], bs2[2], bs2[3]);
        __syncthreads();
        if (tid < 128) {
            float acc2 = 0.f;
            #pragma unroll
            for (int q = 0; q < 16; q++) acc2 += sSh[q * 128 + tid];
            atomicAdd(&g_bnacc[l + 1][blockIdx.x & (NSLOT - 1)][tid], acc2);
        }
    }
}

// ---------------- pooling + MLP head (fused, deterministic) ----------------
__device__ __forceinline__ int lower_bound_dev(const int* b, int n, int v) {
    int lo = 0, hi = n;
    while (lo < hi) {
        int mid = (lo + hi) >> 1;
        if (b[mid] < v) lo = mid + 1; else hi = mid;
    }
    return lo;
}

__global__ void k_pool_mlp(const int* __restrict__ batch,
                           const float* __restrict__ fc1_w,
                           const float* __restrict__ fc1_b,
                           const float* __restrict__ fc2_w,
                           const float* __restrict__ fc2_b,
                           float* __restrict__ out) {
    __shared__ float ps[64];
    __shared__ float r2[2];
    int g = blockIdx.x;
    int tid = threadIdx.x;
    int start = lower_bound_dev(batch, NN, g);
    int end   = lower_bound_dev(batch, NN, g + 1);
    float s = 0.f;
    for (int n = start; n < end; n++) s += g_h[n * 64 + tid];
    ps[tid] = s;
    __syncthreads();
    float z = fc1_b[tid];
    #pragma unroll 8
    for (int k = 0; k < 64; k++) z = fmaf(ps[k], fc1_w[k * 64 + tid], z);
    z = fmaxf(z, 0.0f);
    float p = z * fc2_w[tid];
    #pragma unroll
    for (int off = 16; off > 0; off >>= 1) p += __shfl_down_sync(FULLM, p, off);
    if ((tid & 31) == 0) r2[tid >> 5] = p;
    __syncthreads();
    if (tid == 0) out[g] = fmaxf(r2[0] + r2[1] + fc2_b[0], 0.0f);
}

// ---------------- launcher ----------------
extern "C" void kernel_launch(void* const* d_in, const int* in_sizes, int n_in,
                              void* d_out, int out_size) {
    const float* x         = (const float*)d_in[0];
    const int*   ei        = (const int*)  d_in[1];
    const float* edge_attr = (const float*)d_in[2];
    const int*   batch     = (const int*)  d_in[3];
    const float* lin_w     = (const float*)d_in[4];
    const float* lin_b     = (const float*)d_in[5];
    const float* bn_gamma  = (const float*)d_in[6];
    const float* bn_beta   = (const float*)d_in[7];
    const float* conv_w    = (const float*)d_in[8];
    const float* conv_we   = (const float*)d_in[9];
    const float* att_src   = (const float*)d_in[10];
    const float* att_dst   = (const float*)d_in[11];
    const float* att_edge  = (const float*)d_in[12];
    const float* conv_bias = (const float*)d_in[13];
    const float* fc1_w     = (const float*)d_in[14];
    const float* fc1_b     = (const float*)d_in[15];
    const float* fc2_w     = (const float*)d_in[16];
    const float* fc2_b     = (const float*)d_in[17];
    float* out = (float*)d_out;

    const int smem_cg = (8192 + 4096) * 4;   // 49152 B
    cudaFuncSetAttribute(k_conv_gemm, cudaFuncAttributeMaxDynamicSharedMemorySize, smem_cg);

    // zero deg + bn accumulators; CSR build (reused by all 3 layers)
    k_zero<<<(NN + 255) / 256, 256>>>();
    k_degree<<<(EE + 255) / 256, 256>>>(ei);
    k_scan1<<<NB1, 1024>>>();
    k_scan2<<<1, 256>>>();
    k_scan3<<<NB1, 1024>>>();
    k_fill<<<(EE + 255) / 256, 256>>>(ei);

    // input projection (+ layer-0 BN stats)
    k_lin<<<NN / 8, dim3(64, 8)>>>(x, lin_w, lin_b);

    for (int l = 0; l < 3; l++) {
        k_bnfin<<<1, 256>>>(l, bn_gamma, bn_beta, conv_w, conv_we,
                            att_src, att_dst, att_edge);
        k_bnapply<<<NN / 4, dim3(64, 4)>>>();
        k_escore<<<(EE + 255) / 256, 256>>>(edge_attr);
        k_conv_gemm<<<NN / 32, 256, smem_cg>>>(l, conv_w, conv_bias);
    }

    k_pool_mlp<<<GG, 64>>>(batch, fc1_w, fc1_b, fc2_w, fc2_b, out);
}